// round 1
// baseline (speedup 1.0000x reference)
#include <cuda_runtime.h>
#include <math.h>

#define NB   128   // graphs (B)
#define H    128
#define NPG  8
#define BT   3
#define AA   243   // 3*9*9
#define PAIRS 192  // 8*8*3

__global__ __launch_bounds__(256, 1)
void fused_apm_kernel(const float* __restrict__ nf,      // (1024,128)
                      const float* __restrict__ mask,    // (128,243)
                      const float* __restrict__ Wfcv1,   // (128,64)
                      const float* __restrict__ bfcv1,   // (64)
                      const float* __restrict__ Wfcv2,   // (64,1)
                      const float* __restrict__ bfcv2,   // (1)
                      const float* __restrict__ Wa2,     // (256,128)
                      const float* __restrict__ ba2,     // (128)
                      const float* __restrict__ Wfin,    // (128,3)
                      const float* __restrict__ bfin,    // (3)
                      const int*   __restrict__ idxmask, // (128,243)
                      float* __restrict__ out)           // probs[128*243] ++ readout[128]
{
    const int b = blockIdx.x;
    const int t = threadIdx.x;

    __shared__ float s[NPG][H];          // relu'd node rows of this graph
    __shared__ float ssum[H];            // raw segment sum
    __shared__ float AB[2][NPG][H + 1];  // Ai / Bj, padded stride vs bank conflicts
    __shared__ float sc[PAIRS];          // pair scores, flat (i*8+j)*3+k
    __shared__ float sWf[H * BT];        // W_final
    __shared__ float sba[H];             // b_a2
    __shared__ float red[4];             // readout partial sums
    __shared__ float wred[8];            // softmax warp reductions
    __shared__ float bc[2];              // broadcast max / sum

    // ---- load node rows (relu'd), raw column sums, small weights ----
    for (int idx = t; idx < NPG * H; idx += 256) {
        int n = idx >> 7, c = idx & 127;
        s[n][c] = fmaxf(nf[(b * NPG + n) * H + c], 0.f);
    }
    if (t < H) {
        float acc = 0.f;
        #pragma unroll
        for (int n = 0; n < NPG; n++) acc += nf[(b * NPG + n) * H + t];
        ssum[t] = acc;
        sba[t]  = ba2[t];
    }
    for (int idx = t; idx < H * BT; idx += 256) sWf[idx] = Wfin[idx];
    __syncthreads();

    // ---- Ai / Bj:  AB[g][n][h] = sum_c s[n][c] * Wa2[(g*H + c)*H + h] ----
    {
        const int grp = t >> 7;       // 0 -> Ai, 1 -> Bj
        const int h   = t & 127;
        float acc[NPG];
        #pragma unroll
        for (int n = 0; n < NPG; n++) acc[n] = 0.f;
        const float* W = Wa2 + (grp * H) * H + h;
        #pragma unroll 8
        for (int c = 0; c < H; c++) {
            float w = W[c * H];                    // coalesced, read once per block
            #pragma unroll
            for (int n = 0; n < NPG; n++) acc[n] += s[n][c] * w;  // smem broadcast
        }
        #pragma unroll
        for (int n = 0; n < NPG; n++) AB[grp][n][h] = acc[n];
    }
    __syncthreads();

    // ---- pair scores (warps 0-1) and readout MLP (warps 2-3), concurrently ----
    if (t < 64) {
        const int i = t >> 3, j = t & 7;
        float a0 = bfin[0], a1 = bfin[1], a2 = bfin[2];
        #pragma unroll 4
        for (int h = 0; h < H; h++) {
            float v = AB[0][i][h] + AB[1][j][h] + sba[h];
            v = fmaxf(v, 0.f);
            a0 += v * sWf[h * 3 + 0];
            a1 += v * sWf[h * 3 + 1];
            a2 += v * sWf[h * 3 + 2];
        }
        sc[t * 3 + 0] = a0;
        sc[t * 3 + 1] = a1;
        sc[t * 3 + 2] = a2;
    } else if (t < 128) {
        const int j = t - 64;                     // warps 2,3 fully active
        float acc = bfcv1[j];
        #pragma unroll 4
        for (int c = 0; c < H; c++) acc += ssum[c] * Wfcv1[c * 64 + j];
        float hid = fmaxf(acc, 0.f) * Wfcv2[j];
        #pragma unroll
        for (int off = 16; off > 0; off >>= 1)
            hid += __shfl_down_sync(0xffffffffu, hid, off);
        if ((t & 31) == 0) red[t >> 5] = hid;     // red[2], red[3]
    }
    __syncthreads();

    if (t == 0) out[NB * AA + b] = red[2] + red[3] + bfcv2[0];

    // ---- gather (indexmask) + softmax over 243 ----
    float val = -INFINITY;
    float fv  = 0.f;
    if (t < AA) {
        int im = idxmask[b * AA + t];
        fv = (im < PAIRS) ? sc[im] : 0.f;
        fv += mask[b * AA + t];
        val = fv;
    }
    // block max
    float m = val;
    #pragma unroll
    for (int off = 16; off > 0; off >>= 1)
        m = fmaxf(m, __shfl_xor_sync(0xffffffffu, m, off));
    if ((t & 31) == 0) wred[t >> 5] = m;
    __syncthreads();
    if (t == 0) {
        float mm = wred[0];
        #pragma unroll
        for (int w = 1; w < 8; w++) mm = fmaxf(mm, wred[w]);
        bc[0] = mm;
    }
    __syncthreads();
    float e = (t < AA) ? __expf(fv - bc[0]) : 0.f;
    float ssr = e;
    #pragma unroll
    for (int off = 16; off > 0; off >>= 1)
        ssr += __shfl_xor_sync(0xffffffffu, ssr, off);
    if ((t & 31) == 0) wred[t >> 5] = ssr;
    __syncthreads();
    if (t == 0) {
        float sm = 0.f;
        #pragma unroll
        for (int w = 0; w < 8; w++) sm += wred[w];
        bc[1] = sm;
    }
    __syncthreads();
    if (t < AA) out[b * AA + t] = e / bc[1];
}

extern "C" void kernel_launch(void* const* d_in, const int* in_sizes, int n_in,
                              void* d_out, int out_size) {
    const float* nf     = (const float*)d_in[0];
    // d_in[1] = len_vec     (structure is implied, unused)
    const float* mask   = (const float*)d_in[2];
    const float* Wfcv1  = (const float*)d_in[3];
    const float* bfcv1  = (const float*)d_in[4];
    const float* Wfcv2  = (const float*)d_in[5];
    const float* bfcv2  = (const float*)d_in[6];
    const float* Wa2    = (const float*)d_in[7];
    const float* ba2    = (const float*)d_in[8];
    const float* Wfin   = (const float*)d_in[9];
    const float* bfin   = (const float*)d_in[10];
    const int*   idxm   = (const int*)d_in[11];
    // d_in[12] = segment_ids, d_in[13] = batch_num_nodes (contiguous groups of 8, baked in)
    float* out = (float*)d_out;

    fused_apm_kernel<<<NB, 256>>>(nf, mask, Wfcv1, bfcv1, Wfcv2, bfcv2,
                                  Wa2, ba2, Wfin, bfin, idxm, out);
}

// round 2
// speedup vs baseline: 1.4987x; 1.4987x over previous
#include <cuda_runtime.h>
#include <math.h>

#define NB   128
#define H    128
#define NPG  8
#define BT   3
#define AA   243
#define PAIRS 192
#define TPB  512
#define ABST 132   // padded row stride (floats), 132*4=528B keeps 16B alignment, banks skewed by 4

__global__ __launch_bounds__(TPB, 1)
void fused_apm_kernel(const float* __restrict__ nf,      // (1024,128)
                      const float* __restrict__ mask,    // (128,243)
                      const float* __restrict__ Wfcv1,   // (128,64)
                      const float* __restrict__ bfcv1,   // (64)
                      const float* __restrict__ Wfcv2,   // (64,1)
                      const float* __restrict__ bfcv2,   // (1)
                      const float* __restrict__ Wa2,     // (256,128)
                      const float* __restrict__ ba2,     // (128)
                      const float* __restrict__ Wfin,    // (128,3)
                      const float* __restrict__ bfin,    // (3)
                      const int*   __restrict__ idxmask, // (128,243)
                      float* __restrict__ out)           // probs[128*243] ++ readout[128]
{
    const int b = blockIdx.x;
    const int t = threadIdx.x;

    __shared__ __align__(16) float s[NPG][H];       // relu'd node rows
    __shared__ __align__(16) float ssum[H];         // raw segment sum
    __shared__ __align__(16) float AB[2][NPG][ABST];
    __shared__ float sc[PAIRS];
    __shared__ __align__(16) float sWfT[BT][H];     // W_final transposed
    __shared__ __align__(16) float sba[H];
    __shared__ float red[8];
    __shared__ float wred[16];
    __shared__ float bc[2];

    // ---- stage inputs ----
    for (int idx = t; idx < NPG * H; idx += TPB) {
        int n = idx >> 7, c = idx & 127;
        s[n][c] = fmaxf(nf[(b * NPG + n) * H + c], 0.f);
    }
    if (t < H) {
        float a = 0.f;
        #pragma unroll
        for (int n = 0; n < NPG; n++) a += nf[(b * NPG + n) * H + t];
        ssum[t] = a;
        sba[t]  = ba2[t];
    } else if (t < H + H * BT) {
        int idx = t - H;                // 0..383
        int h = idx & 127, k = idx >> 7;
        sWfT[k][h] = Wfin[h * BT + k];
    }
    __syncthreads();

    // ---- Ai/Bj GEMM: thread = (np, grp, h), 4 nodes each, float4 smem reads ----
    {
        const int h   = t & 127;
        const int grp = (t >> 7) & 1;
        const int np  = t >> 8;                 // node half: 0 -> nodes 0-3, 1 -> 4-7
        float acc0 = 0.f, acc1 = 0.f, acc2 = 0.f, acc3 = 0.f;
        const float* W = Wa2 + grp * H * H + h;
        const float4* s40 = reinterpret_cast<const float4*>(s[np * 4 + 0]);
        const float4* s41 = reinterpret_cast<const float4*>(s[np * 4 + 1]);
        const float4* s42 = reinterpret_cast<const float4*>(s[np * 4 + 2]);
        const float4* s43 = reinterpret_cast<const float4*>(s[np * 4 + 3]);
        #pragma unroll 4
        for (int c4 = 0; c4 < H / 4; c4++) {
            const int c = c4 * 4;
            float w0 = W[(c + 0) * H];
            float w1 = W[(c + 1) * H];
            float w2 = W[(c + 2) * H];
            float w3 = W[(c + 3) * H];
            float4 v;
            v = s40[c4]; acc0 += v.x * w0 + v.y * w1 + v.z * w2 + v.w * w3;
            v = s41[c4]; acc1 += v.x * w0 + v.y * w1 + v.z * w2 + v.w * w3;
            v = s42[c4]; acc2 += v.x * w0 + v.y * w1 + v.z * w2 + v.w * w3;
            v = s43[c4]; acc3 += v.x * w0 + v.y * w1 + v.z * w2 + v.w * w3;
        }
        AB[grp][np * 4 + 0][h] = acc0;
        AB[grp][np * 4 + 1][h] = acc1;
        AB[grp][np * 4 + 2][h] = acc2;
        AB[grp][np * 4 + 3][h] = acc3;
    }
    __syncthreads();

    // ---- pair scores (warps 0-5, one thread per (pair,k)) + readout (warps 6-7) ----
    if (t < PAIRS) {
        const int k = t >> 6;            // warps {0,1}->k0, {2,3}->k1, {4,5}->k2
        const int p = t & 63;
        const int i = p >> 3, j = p & 7;
        const float4* A4 = reinterpret_cast<const float4*>(AB[0][i]);
        const float4* B4 = reinterpret_cast<const float4*>(AB[1][j]);
        const float4* W4 = reinterpret_cast<const float4*>(sWfT[k]);
        const float4* Z4 = reinterpret_cast<const float4*>(sba);
        float acc = bfin[k];
        #pragma unroll 8
        for (int hq = 0; hq < H / 4; hq++) {
            float4 a = A4[hq], bb = B4[hq], w = W4[hq], z = Z4[hq];
            acc += fmaxf(a.x + bb.x + z.x, 0.f) * w.x
                 + fmaxf(a.y + bb.y + z.y, 0.f) * w.y
                 + fmaxf(a.z + bb.z + z.z, 0.f) * w.z
                 + fmaxf(a.w + bb.w + z.w, 0.f) * w.w;
        }
        sc[p * BT + k] = acc;
    } else if (t < 256) {
        const int j = t - PAIRS;         // 0..63
        float acc = bfcv1[j];
        const float4* S4 = reinterpret_cast<const float4*>(ssum);
        #pragma unroll 8
        for (int c4 = 0; c4 < H / 4; c4++) {
            float4 sv = S4[c4];
            const int c = c4 * 4;
            acc += sv.x * Wfcv1[(c + 0) * 64 + j]
                 + sv.y * Wfcv1[(c + 1) * 64 + j]
                 + sv.z * Wfcv1[(c + 2) * 64 + j]
                 + sv.w * Wfcv1[(c + 3) * 64 + j];
        }
        float hid = fmaxf(acc, 0.f) * Wfcv2[j];
        #pragma unroll
        for (int off = 16; off > 0; off >>= 1)
            hid += __shfl_down_sync(0xffffffffu, hid, off);
        if ((t & 31) == 0) red[t >> 5] = hid;   // red[6], red[7]
    }
    __syncthreads();

    if (t == 0) out[NB * AA + b] = red[6] + red[7] + bfcv2[0];

    // ---- gather + softmax over 243 (all 16 warps participate in reductions) ----
    float fv = 0.f, val = -INFINITY;
    if (t < AA) {
        int im = idxmask[b * AA + t];
        fv = ((im < PAIRS) ? sc[im] : 0.f) + mask[b * AA + t];
        val = fv;
    }
    float m = val;
    #pragma unroll
    for (int off = 16; off > 0; off >>= 1)
        m = fmaxf(m, __shfl_xor_sync(0xffffffffu, m, off));
    if ((t & 31) == 0) wred[t >> 5] = m;
    __syncthreads();
    if (t == 0) {
        float mm = wred[0];
        #pragma unroll
        for (int w = 1; w < 16; w++) mm = fmaxf(mm, wred[w]);
        bc[0] = mm;
    }
    __syncthreads();
    float e = (t < AA) ? __expf(fv - bc[0]) : 0.f;
    float sr = e;
    #pragma unroll
    for (int off = 16; off > 0; off >>= 1)
        sr += __shfl_xor_sync(0xffffffffu, sr, off);
    if ((t & 31) == 0) wred[t >> 5] = sr;
    __syncthreads();
    if (t == 0) {
        float sm = 0.f;
        #pragma unroll
        for (int w = 0; w < 16; w++) sm += wred[w];
        bc[1] = sm;
    }
    __syncthreads();
    if (t < AA) out[b * AA + t] = e / bc[1];
}

extern "C" void kernel_launch(void* const* d_in, const int* in_sizes, int n_in,
                              void* d_out, int out_size) {
    const float* nf     = (const float*)d_in[0];
    const float* mask   = (const float*)d_in[2];
    const float* Wfcv1  = (const float*)d_in[3];
    const float* bfcv1  = (const float*)d_in[4];
    const float* Wfcv2  = (const float*)d_in[5];
    const float* bfcv2  = (const float*)d_in[6];
    const float* Wa2    = (const float*)d_in[7];
    const float* ba2    = (const float*)d_in[8];
    const float* Wfin   = (const float*)d_in[9];
    const float* bfin   = (const float*)d_in[10];
    const int*   idxm   = (const int*)d_in[11];
    float* out = (float*)d_out;

    fused_apm_kernel<<<NB, TPB>>>(nf, mask, Wfcv1, bfcv1, Wfcv2, bfcv2,
                                  Wa2, ba2, Wfin, bfin, idxm, out);
}